// round 16
// baseline (speedup 1.0000x reference)
#include <cuda_runtime.h>
#include <cuda_fp16.h>
#include <cstdint>
#include <cstddef>

#define NN 50000
#define NE 800000
#define DD 64
#define HH 128

// padded SMEM strides (elements); stride*2B mod 128B == 16B -> ldmatrix conflict-free
#define XS  200
#define HS  136
#define W1S 200
#define W2S 136
#define YS  68

// SMEM byte offsets (single-fp16 layout, fits 2 CTAs/SM)
#define OFF_W1  0        // 128*200*2 = 51200
#define OFF_W2  51200    // 64*136*2 = 17408
#define OFF_X   68608    // 64*200*2 = 25600 (fp16; fp32 Y aliases here)
#define OFF_H   94208    // 64*136*2 = 17408
#define OFF_B1  111616
#define OFF_B2  112128
#define OFF_G   112384
#define OFF_BT  112640
#define OFF_EIX 112896
#define SMEM_BYTES 113920

// ---------------- scratch ----------------
__device__ float g_sum_src[(size_t)NN * DD];
__device__ float g_sum_dst[(size_t)NN * DD];
__device__ float g_cnt_src[NN];
__device__ float g_cnt_dst[NN];

// ---------------- helpers ----------------
// tanh-GELU via MUFU: gelu(x) = x·E/(1+E), E = 2^z, z = 2u·log2(e)
__device__ __forceinline__ float gelu_f(float x) {
    float z = x * fmaf(0.10293917f, x * x, 2.3021183f);
    float E;
    asm("ex2.approx.f32 %0, %1;" : "=f"(E) : "f"(z));
    float d = 1.0f + E;
    float r;
    asm("rcp.approx.f32 %0, %1;" : "=f"(r) : "f"(d));
    return fmaf(-x, r, x);   // x - x/(1+E)
}
__device__ __forceinline__ float rcp_fast(float x) {
    float r;
    asm("rcp.approx.f32 %0, %1;" : "=f"(r) : "f"(x));
    return r;
}

__device__ __forceinline__ void red_add4(float* p, float a, float b, float c, float d) {
    asm volatile("red.global.add.v4.f32 [%0], {%1, %2, %3, %4};"
                 :: "l"(p), "f"(a), "f"(b), "f"(c), "f"(d) : "memory");
}
__device__ __forceinline__ void red_add1(float* p, float a) {
    asm volatile("red.global.add.f32 [%0], %1;" :: "l"(p), "f"(a) : "memory");
}

__device__ __forceinline__ void mma_fp16(float (&c)[4],
                                         uint32_t a0, uint32_t a1, uint32_t a2, uint32_t a3,
                                         uint32_t b0, uint32_t b1) {
    asm volatile("mma.sync.aligned.m16n8k16.row.col.f32.f16.f16.f32 "
                 "{%0,%1,%2,%3}, {%4,%5,%6,%7}, {%8,%9}, {%0,%1,%2,%3};"
                 : "+f"(c[0]), "+f"(c[1]), "+f"(c[2]), "+f"(c[3])
                 : "r"(a0), "r"(a1), "r"(a2), "r"(a3), "r"(b0), "r"(b1));
}
__device__ __forceinline__ void ldsm4(uint32_t& r0, uint32_t& r1, uint32_t& r2, uint32_t& r3,
                                      uint32_t a) {
    asm volatile("ldmatrix.sync.aligned.m8n8.x4.shared.b16 {%0,%1,%2,%3}, [%4];"
                 : "=r"(r0), "=r"(r1), "=r"(r2), "=r"(r3) : "r"(a));
}
__device__ __forceinline__ uint32_t smem_u32(const void* p) {
    return (uint32_t)__cvta_generic_to_shared(p);
}
__device__ __forceinline__ uint32_t pack_h2(float a, float b) {
    __half2 v = __floats2half2_rn(a, b);
    return *(uint32_t*)&v;
}

// ---------------- weight/bias load (256 threads, single fp16) ----------------
__device__ __forceinline__ void load_weights(char* smem,
                                             const float* __restrict__ W1, const float* __restrict__ b1,
                                             const float* __restrict__ W2, const float* __restrict__ b2,
                                             const float* __restrict__ gam, const float* __restrict__ bet,
                                             int t) {
    __half* W1s = (__half*)(smem + OFF_W1);
    __half* W2s = (__half*)(smem + OFF_W2);
    float* b1s = (float*)(smem + OFF_B1);
    float* b2s = (float*)(smem + OFF_B2);
    float* gs  = (float*)(smem + OFF_G);
    float* bts = (float*)(smem + OFF_BT);

    for (int i = t; i < 192 * HH; i += 256) {
        int k = i >> 7, n = i & 127;
        W1s[n * W1S + k] = __float2half_rn(W1[i]);   // transposed [n][k]
    }
    for (int i = t; i < HH * DD; i += 256) {
        int k = i >> 6, n = i & 63;
        W2s[n * W2S + k] = __float2half_rn(W2[i]);
    }
    if (t < 128) b1s[t] = b1[t];
    if (t < 64) { b2s[t] = b2[t]; gs[t] = gam[t]; bts[t] = bet[t]; }
}

// ---------------- 64-row tile MLP (256 threads / 8 warps, fp16 single) ----------------
__device__ __forceinline__ void mlp_tile_tc(char* smem, int t) {
    const __half* W1s = (const __half*)(smem + OFF_W1);
    const __half* W2s = (const __half*)(smem + OFF_W2);
    const __half* Xs  = (const __half*)(smem + OFF_X);
    __half* Hs = (__half*)(smem + OFF_H);
    float* Ys = (float*)(smem + OFF_X);   // alias: X dead after GEMM1 sync
    const float* b1s = (const float*)(smem + OFF_B1);
    const float* b2s = (const float*)(smem + OFF_B2);

    const int warp = t >> 5, lane = t & 31;
    const int g = lane >> 2, tg = lane & 3;
    const int m0 = (warp >> 1) * 16;
    const int lrow = lane & 15;
    const int akh  = (lane >> 4) & 1;
    const int brow = lane & 7;
    const int bkh  = (lane >> 3) & 1;
    const int bnt  = (lane >> 4) & 1;

    // ---------------- GEMM1: [64,192]x[192,128], warp tile 16x64 ----------------
    {
        const int n0 = (warp & 1) * 64;
        float C[8][4];
#pragma unroll
        for (int nt = 0; nt < 8; nt++) {
            float bv0 = b1s[n0 + nt * 8 + 2 * tg];
            float bv1 = b1s[n0 + nt * 8 + 2 * tg + 1];
            C[nt][0] = bv0; C[nt][1] = bv1; C[nt][2] = bv0; C[nt][3] = bv1;
        }
        uint32_t aX = smem_u32(Xs + (m0 + lrow) * XS) + akh * 16;
        uint32_t b0a = smem_u32(W1s + (n0 + (0 + bnt) * 8 + brow) * W1S) + bkh * 16;
        uint32_t b1a = smem_u32(W1s + (n0 + (2 + bnt) * 8 + brow) * W1S) + bkh * 16;
        uint32_t b2a = smem_u32(W1s + (n0 + (4 + bnt) * 8 + brow) * W1S) + bkh * 16;
        uint32_t b3a = smem_u32(W1s + (n0 + (6 + bnt) * 8 + brow) * W1S) + bkh * 16;
#pragma unroll
        for (int ks = 0; ks < 12; ks++) {
            const uint32_t off = ks * 32;
            uint32_t a0, a1, a2, a3;
            ldsm4(a0, a1, a2, a3, aX + off);
            uint32_t p0, p1, p2, p3;
            ldsm4(p0, p1, p2, p3, b0a + off);
            uint32_t q0, q1, q2, q3;
            ldsm4(q0, q1, q2, q3, b1a + off);
            mma_fp16(C[0], a0, a1, a2, a3, p0, p1);
            mma_fp16(C[1], a0, a1, a2, a3, p2, p3);
            mma_fp16(C[2], a0, a1, a2, a3, q0, q1);
            mma_fp16(C[3], a0, a1, a2, a3, q2, q3);
            uint32_t r0, r1, r2, r3;
            ldsm4(r0, r1, r2, r3, b2a + off);
            uint32_t s0, s1, s2, s3;
            ldsm4(s0, s1, s2, s3, b3a + off);
            mma_fp16(C[4], a0, a1, a2, a3, r0, r1);
            mma_fp16(C[5], a0, a1, a2, a3, r2, r3);
            mma_fp16(C[6], a0, a1, a2, a3, s0, s1);
            mma_fp16(C[7], a0, a1, a2, a3, s2, s3);
        }
        // GELU -> fp16 H
#pragma unroll
        for (int nt = 0; nt < 8; nt++) {
            const int col = n0 + nt * 8 + 2 * tg;
            float y0 = gelu_f(C[nt][0]);
            float y1 = gelu_f(C[nt][1]);
            float y2 = gelu_f(C[nt][2]);
            float y3 = gelu_f(C[nt][3]);
            *(__half2*)(Hs + (m0 + g) * HS + col)     = __floats2half2_rn(y0, y1);
            *(__half2*)(Hs + (m0 + g + 8) * HS + col) = __floats2half2_rn(y2, y3);
        }
    }
    __syncthreads();   // H complete; X reads done (Y alias safe)

    // ---------------- GEMM2: [64,128]x[128,64], warp tile 16x32 ----------------
    {
        const int n0 = (warp & 1) * 32;
        float C[4][4];
#pragma unroll
        for (int nt = 0; nt < 4; nt++) {
            float bv0 = b2s[n0 + nt * 8 + 2 * tg];
            float bv1 = b2s[n0 + nt * 8 + 2 * tg + 1];
            C[nt][0] = bv0; C[nt][1] = bv1; C[nt][2] = bv0; C[nt][3] = bv1;
        }
        uint32_t aH = smem_u32(Hs + (m0 + lrow) * HS) + akh * 16;
        uint32_t b0a = smem_u32(W2s + (n0 + (0 + bnt) * 8 + brow) * W2S) + bkh * 16;
        uint32_t b1a = smem_u32(W2s + (n0 + (2 + bnt) * 8 + brow) * W2S) + bkh * 16;
#pragma unroll
        for (int ks = 0; ks < 8; ks++) {
            const uint32_t off = ks * 32;
            uint32_t a0, a1, a2, a3;
            ldsm4(a0, a1, a2, a3, aH + off);
            uint32_t p0, p1, p2, p3;
            ldsm4(p0, p1, p2, p3, b0a + off);
            uint32_t q0, q1, q2, q3;
            ldsm4(q0, q1, q2, q3, b1a + off);
            mma_fp16(C[0], a0, a1, a2, a3, p0, p1);
            mma_fp16(C[1], a0, a1, a2, a3, p2, p3);
            mma_fp16(C[2], a0, a1, a2, a3, q0, q1);
            mma_fp16(C[3], a0, a1, a2, a3, q2, q3);
        }
#pragma unroll
        for (int nt = 0; nt < 4; nt++) {
            const int col = n0 + nt * 8 + 2 * tg;
            *(float2*)(Ys + (m0 + g) * YS + col)     = make_float2(C[nt][0], C[nt][1]);
            *(float2*)(Ys + (m0 + g + 8) * YS + col) = make_float2(C[nt][2], C[nt][3]);
        }
    }
    __syncthreads();   // Y visible to LN
}

// ---------------- edge kernel (2 CTAs/SM, register-prefetched gather) ----------------
__global__ __launch_bounds__(256, 2)
void edge_kernel(const float* __restrict__ ndata, const float* __restrict__ edata,
                 const int* __restrict__ src, const int* __restrict__ dst,
                 const float* __restrict__ W1, const float* __restrict__ b1,
                 const float* __restrict__ W2, const float* __restrict__ b2,
                 const float* __restrict__ gam, const float* __restrict__ bet,
                 float* __restrict__ eout, int write_out) {
    extern __shared__ char smem[];
    const int t = threadIdx.x;
    load_weights(smem, W1, b1, W2, b2, gam, bet, t);

    __half* Xs = (__half*)(smem + OFF_X);
    float* Ys  = (float*)(smem + OFF_X);
    const float* gs  = (const float*)(smem + OFF_G);
    const float* bts = (const float*)(smem + OFF_BT);
    int* eidx_base = (int*)(smem + OFF_EIX);   // 2 x 128

    const int numTiles = NE / 64;  // 12500
    const int stride = gridDim.x;
    int tile = blockIdx.x;

    if (t < 128) {
        int e0 = tile * 64;
        eidx_base[t] = (t < 64) ? src[e0 + t] : dst[e0 + (t - 64)];
    }
    __syncthreads();

    uint2 vals[12];
    auto prefetch = [&](const int* eidx, int e0) {
#pragma unroll
        for (int j = 0; j < 12; j++) {
            int f = t + j * 256;
            int e = f / 48, p = f % 48;
            float4 v;
            if (p < 16)
                v = *(const float4*)(ndata + (size_t)eidx[e] * DD + p * 4);
            else if (p < 32)
                v = *(const float4*)(ndata + (size_t)eidx[64 + e] * DD + (p - 16) * 4);
            else
                v = *(const float4*)(edata + (size_t)(e0 + e) * DD + (p - 32) * 4);
            vals[j].x = pack_h2(v.x, v.y);
            vals[j].y = pack_h2(v.z, v.w);
        }
    };
    auto store_vals = [&]() {
#pragma unroll
        for (int j = 0; j < 12; j++) {
            int f = t + j * 256;
            int e = f / 48, p = f % 48;
            *(uint2*)(Xs + e * XS + p * 4) = vals[j];
        }
    };

    prefetch(eidx_base, tile * 64);
    store_vals();

    int buf = 0;
    for (;;) {
        const int next = tile + stride;
        const bool has_next = next < numTiles;
        const int* eidx_cur = eidx_base + buf * 128;
        int* eidx_nxt = eidx_base + (buf ^ 1) * 128;

        if (has_next && t < 128) {
            int e0n = next * 64;
            eidx_nxt[t] = (t < 64) ? src[e0n + t] : dst[e0n + (t - 64)];
        }
        __syncthreads();   // X stores visible; eidx_nxt visible

        if (has_next) prefetch(eidx_base + (buf ^ 1) * 128, next * 64);

        mlp_tile_tc(smem, t);

        // LayerNorm + output + scatter (8 warps x 8 rows, half-warp per row)
        {
            const int e0 = tile * 64;
            const int warp = t >> 5, lane = t & 31;
            const int half = lane >> 4, l16 = lane & 15;
#pragma unroll
            for (int it = 0; it < 4; ++it) {
                int row = warp * 8 + it * 2 + half;
                float ya[4];
                *(float4*)ya = *(const float4*)(Ys + row * YS + l16 * 4);
                float s  = ya[0] + ya[1] + ya[2] + ya[3];
                float ss = ya[0]*ya[0] + ya[1]*ya[1] + ya[2]*ya[2] + ya[3]*ya[3];
#pragma unroll
                for (int o = 8; o; o >>= 1) {
                    s  += __shfl_xor_sync(0xffffffffu, s, o);
                    ss += __shfl_xor_sync(0xffffffffu, ss, o);
                }
                float mu  = s * (1.0f / 64.0f);
                float var = ss * (1.0f / 64.0f) - mu * mu;
                float rs  = rsqrtf(var + 1e-5f);
                float o4[4];
#pragma unroll
                for (int j = 0; j < 4; j++) {
                    int c = l16 * 4 + j;
                    o4[j] = (ya[j] - mu) * rs * gs[c] + bts[c];
                }
                if (write_out)
                    *(float4*)(eout + (size_t)(e0 + row) * DD + l16 * 4) = *(float4*)o4;
                int sn = eidx_cur[row], dn = eidx_cur[64 + row];
                red_add4(g_sum_src + (size_t)sn * DD + l16 * 4, o4[0], o4[1], o4[2], o4[3]);
                red_add4(g_sum_dst + (size_t)dn * DD + l16 * 4, o4[0], o4[1], o4[2], o4[3]);
                if (l16 == 0) {
                    red_add1(g_cnt_src + sn, 1.0f);
                    red_add1(g_cnt_dst + dn, 1.0f);
                }
            }
        }

        if (!has_next) return;
        __syncthreads();   // Ys (X alias) + eidx_cur consumed

        store_vals();
        buf ^= 1;
        tile = next;
    }
}

// ---------------- node kernel (grid 152: weights amortized over ~5 tiles) ----------------
__global__ __launch_bounds__(256, 2)
void node_kernel(const float* __restrict__ ndata,
                 const float* __restrict__ W1, const float* __restrict__ b1,
                 const float* __restrict__ W2, const float* __restrict__ b2,
                 const float* __restrict__ gam, const float* __restrict__ bet,
                 float* __restrict__ nout) {
    extern __shared__ char smem[];
    const int t = threadIdx.x;
    load_weights(smem, W1, b1, W2, b2, gam, bet, t);

    __half* Xs = (__half*)(smem + OFF_X);
    float* Ys  = (float*)(smem + OFF_X);
    const float* gs  = (const float*)(smem + OFF_G);
    const float* bts = (const float*)(smem + OFF_BT);

    const int numTiles = (NN + 63) / 64;   // 782
    const int stride = gridDim.x;
    int tile = blockIdx.x;

    uint2 vals[12];
    auto prefetch = [&](int tl) {
#pragma unroll
        for (int j = 0; j < 12; j++) {
            int f = t + j * 256;
            int r = f / 48, p = f % 48;
            int n = tl * 64 + r;
            float4 v = make_float4(0.f, 0.f, 0.f, 0.f);
            if (n < NN) {
                if (p < 16) {
                    float ic = rcp_fast(fmaxf(g_cnt_src[n], 1.0f));
                    float4 s4 = *(const float4*)(g_sum_src + (size_t)n * DD + p * 4);
                    v = make_float4(s4.x * ic, s4.y * ic, s4.z * ic, s4.w * ic);
                } else if (p < 32) {
                    float ic = rcp_fast(fmaxf(g_cnt_dst[n], 1.0f));
                    float4 s4 = *(const float4*)(g_sum_dst + (size_t)n * DD + (p - 16) * 4);
                    v = make_float4(s4.x * ic, s4.y * ic, s4.z * ic, s4.w * ic);
                } else {
                    v = *(const float4*)(ndata + (size_t)n * DD + (p - 32) * 4);
                }
            }
            vals[j].x = pack_h2(v.x, v.y);
            vals[j].y = pack_h2(v.z, v.w);
        }
    };
    auto store_vals = [&]() {
#pragma unroll
        for (int j = 0; j < 12; j++) {
            int f = t + j * 256;
            int r = f / 48, p = f % 48;
            *(uint2*)(Xs + r * XS + p * 4) = vals[j];
        }
    };

    if (tile < numTiles) {
        prefetch(tile);
        store_vals();
    }

    for (; tile < numTiles; ) {
        __syncthreads();   // X + weights visible

        const int next = tile + stride;
        const bool has_next = next < numTiles;
        if (has_next) prefetch(next);   // overlaps with MMAs

        mlp_tile_tc(smem, t);

        {
            const int n0 = tile * 64;
            const int warp = t >> 5, lane = t & 31;
            const int half = lane >> 4, l16 = lane & 15;
#pragma unroll
            for (int it = 0; it < 4; ++it) {
                int row = warp * 8 + it * 2 + half;
                float ya[4];
                *(float4*)ya = *(const float4*)(Ys + row * YS + l16 * 4);
                float s  = ya[0] + ya[1] + ya[2] + ya[3];
                float ss = ya[0]*ya[0] + ya[1]*ya[1] + ya[2]*ya[2] + ya[3]*ya[3];
#pragma unroll
                for (int o = 8; o; o >>= 1) {
                    s  += __shfl_xor_sync(0xffffffffu, s, o);
                    ss += __shfl_xor_sync(0xffffffffu, ss, o);
                }
                float mu  = s * (1.0f / 64.0f);
                float var = ss * (1.0f / 64.0f) - mu * mu;
                float rs  = rsqrtf(var + 1e-5f);
                int n = n0 + row;
                if (n < NN) {
                    float o4[4];
#pragma unroll
                    for (int j = 0; j < 4; j++) {
                        int c = l16 * 4 + j;
                        o4[j] = (ya[j] - mu) * rs * gs[c] + bts[c];
                    }
                    *(float4*)(nout + (size_t)n * DD + l16 * 4) = *(float4*)o4;
                }
            }
        }

        if (!has_next) break;
        __syncthreads();   // Ys consumed
        store_vals();
        tile = next;
    }
}

// ---------------- launch ----------------
extern "C" void kernel_launch(void* const* d_in, const int* in_sizes, int n_in,
                              void* d_out, int out_size) {
    const float* ndata = (const float*)d_in[0];
    const float* edata = (const float*)d_in[1];
    const int*   src   = (const int*)d_in[2];
    const int*   dst   = (const int*)d_in[3];
    const float* eW1 = (const float*)d_in[4];
    const float* eb1 = (const float*)d_in[5];
    const float* eW2 = (const float*)d_in[6];
    const float* eb2 = (const float*)d_in[7];
    const float* eg  = (const float*)d_in[8];
    const float* ebt = (const float*)d_in[9];
    const float* nW1 = (const float*)d_in[10];
    const float* nb1 = (const float*)d_in[11];
    const float* nW2 = (const float*)d_in[12];
    const float* nb2 = (const float*)d_in[13];
    const float* ng  = (const float*)d_in[14];
    const float* nbt = (const float*)d_in[15];

    float* out  = (float*)d_out;
    float* nout = out;                        // ndata_new first
    float* eout = out + (size_t)NN * DD;      // edata_new second
    int write_edges = (out_size >= (NN + NE) * DD) ? 1 : 0;

    int sm = 148;
    cudaDeviceGetAttribute(&sm, cudaDevAttrMultiProcessorCount, 0);

    cudaFuncSetAttribute(edge_kernel, cudaFuncAttributeMaxDynamicSharedMemorySize, SMEM_BYTES);
    cudaFuncSetAttribute(node_kernel, cudaFuncAttributeMaxDynamicSharedMemorySize, SMEM_BYTES);

    void *p_ss, *p_sd, *p_cs, *p_cd;
    cudaGetSymbolAddress(&p_ss, g_sum_src);
    cudaGetSymbolAddress(&p_sd, g_sum_dst);
    cudaGetSymbolAddress(&p_cs, g_cnt_src);
    cudaGetSymbolAddress(&p_cd, g_cnt_dst);
    cudaMemsetAsync(p_ss, 0, (size_t)NN * DD * sizeof(float), 0);
    cudaMemsetAsync(p_sd, 0, (size_t)NN * DD * sizeof(float), 0);
    cudaMemsetAsync(p_cs, 0, (size_t)NN * sizeof(float), 0);
    cudaMemsetAsync(p_cd, 0, (size_t)NN * sizeof(float), 0);

    edge_kernel<<<2 * sm, 256, SMEM_BYTES>>>(ndata, edata, src, dst,
                                             eW1, eb1, eW2, eb2, eg, ebt,
                                             eout, write_edges);
    node_kernel<<<sm, 256, SMEM_BYTES>>>(ndata, nW1, nb1, nW2, nb2, ng, nbt, nout);
}